// round 17
// baseline (speedup 1.0000x reference)
#include <cuda_runtime.h>
#include <cuda_fp16.h>
#include <cstdint>

#define B_   2
#define S_   2048
#define D_   1024
#define H_   16
#define DK_  64
#define MTOT (B_ * S_)   // 4096

// ---------------------------------------------------------------------------
// Scratch (device globals — no allocation allowed). All fp16 intermediates.
// ---------------------------------------------------------------------------
__device__ __half g_Q[MTOT * D_];        // pre-scaled by log2(e)/8
__device__ __half g_K[MTOT * D_];
__device__ __half g_V[MTOT * D_];
__device__ __half g_att[MTOT * D_];
__device__ __half g_x16[MTOT * D_];
__device__ __half g_w16[4 * D_ * D_];

// ---------------------------------------------------------------------------
// Helpers (baseline PTX only: cp.async, ldmatrix, mma.m16n8k16.f16, ex2.f16x2)
// ---------------------------------------------------------------------------
__device__ __forceinline__ uint32_t smem_u32(const void* p) {
    uint32_t a;
    asm("{ .reg .u64 t; cvta.to.shared.u64 t, %1; cvt.u32.u64 %0, t; }"
        : "=r"(a) : "l"(p));
    return a;
}
__device__ __forceinline__ void cp16(uint32_t s, const void* g) {
    asm volatile("cp.async.cg.shared.global [%0], [%1], 16;"
                 :: "r"(s), "l"(g) : "memory");
}
#define CP_COMMIT() asm volatile("cp.async.commit_group;" ::: "memory")
#define CP_WAIT(n)  asm volatile("cp.async.wait_group %0;" :: "n"(n) : "memory")

__device__ __forceinline__ void ldsm4(uint32_t* r, uint32_t addr) {
    asm volatile("ldmatrix.sync.aligned.m8n8.x4.shared.b16 {%0,%1,%2,%3}, [%4];"
                 : "=r"(r[0]), "=r"(r[1]), "=r"(r[2]), "=r"(r[3]) : "r"(addr));
}
__device__ __forceinline__ void ldsm4t(uint32_t* r, uint32_t addr) {
    asm volatile("ldmatrix.sync.aligned.m8n8.x4.trans.shared.b16 {%0,%1,%2,%3}, [%4];"
                 : "=r"(r[0]), "=r"(r[1]), "=r"(r[2]), "=r"(r[3]) : "r"(addr));
}
__device__ __forceinline__ void mma_f16(float* c, const uint32_t* a,
                                        uint32_t b0, uint32_t b1) {
    asm volatile(
        "mma.sync.aligned.m16n8k16.row.col.f32.f16.f16.f32 "
        "{%0,%1,%2,%3}, {%4,%5,%6,%7}, {%8,%9}, {%0,%1,%2,%3};"
        : "+f"(c[0]), "+f"(c[1]), "+f"(c[2]), "+f"(c[3])
        : "r"(a[0]), "r"(a[1]), "r"(a[2]), "r"(a[3]), "r"(b0), "r"(b1));
}
// two fp16 exp2 in one MUFU op
__device__ __forceinline__ __half2 hexp2_(__half2 x) {
    uint32_t r, xi = *(uint32_t*)&x;
    asm("ex2.approx.f16x2 %0, %1;" : "=r"(r) : "r"(xi));
    return *(__half2*)&r;
}

// ---------------------------------------------------------------------------
// Prep (single launch): fp32 -> fp16 for x and all 4 weights.
// ---------------------------------------------------------------------------
__global__ __launch_bounds__(256) void cvt_all(const float* __restrict__ x,
                                               const float* __restrict__ w0,
                                               const float* __restrict__ w1,
                                               const float* __restrict__ w2,
                                               const float* __restrict__ w3,
                                               __half2* __restrict__ xo,
                                               __half2* __restrict__ wo)
{
    int bid = blockIdx.x;
    const float* src;
    __half2* dst;
    int local;
    if (bid < 4096) {
        src = x; dst = xo; local = bid;
    } else {
        int wsel = (bid - 4096) >> 10;
        src = (wsel == 0) ? w0 : (wsel == 1) ? w1 : (wsel == 2) ? w2 : w3;
        dst = wo + (size_t)wsel * (D_ * D_ / 2);
        local = (bid - 4096) & 1023;
    }
    int i = local * 256 + threadIdx.x;
    float4 v = ((const float4*)src)[i];
    dst[2 * i + 0] = __floats2half2_rn(v.x, v.y);
    dst[2 * i + 1] = __floats2half2_rn(v.z, v.w);
}

// ---------------------------------------------------------------------------
// fp16 GEMM, occupancy-4 variant: 128x64 tile, 256 thr / 8 warps (2M x 4N,
// warp tile 64x16, acc 32 regs -> fits 64-reg cap of 4 CTAs/SM).
// KCH 64, 2-stage cp.async double buffer (55296 B smem -> 4 CTAs = 221 KB).
// Same K-accumulation order as R15 -> bit-identical results.
// ---------------------------------------------------------------------------
#define KCH     64
#define AP      72
#define BPn     72
#define AHALFS  (128 * AP)               // 9216
#define BHALFS  (KCH * BPn)              // 4608
#define STAGEH  (AHALFS + BHALFS)        // 13824 halfs
#define STAGEB  (STAGEH * 2)             // 27648 B
#define GSMEM   (2 * STAGEB)             // 55296 B

template <int MODE>
__device__ __forceinline__ void gemm_body(const __half* __restrict__ A,
                                          const __half* __restrict__ W,
                                          void* __restrict__ C,
                                          int bx, int by, float scale,
                                          __half* smh)
{
    const int tid  = threadIdx.x;
    const int wid  = tid >> 5;
    const int lane = tid & 31;
    const int g    = lane >> 2;
    const int tig  = lane & 3;
    const int ml   = lane >> 3;
    const int rw   = lane & 7;
    const int m0w  = (wid >> 2) * 64;    // 2 M-warps
    const int n0w  = (wid & 3) * 16;     // 4 N-warps
    const int N    = D_;

    const __half* Ab = A + (size_t)by * 128 * D_;
    const uint32_t sbase = smem_u32(smh);

    float acc[4][2][4];
#pragma unroll
    for (int i = 0; i < 4; i++)
#pragma unroll
        for (int j = 0; j < 2; j++)
#pragma unroll
            for (int q = 0; q < 4; q++) acc[i][j][q] = 0.f;

    const int NC = D_ / KCH;   // 16

    auto copy_chunk = [&](int c, int buf) {
        const __half* Ac = Ab + c * KCH;
        const __half* Bc = W + (size_t)c * KCH * D_ + bx * 64;
        uint32_t ab = sbase + (uint32_t)buf * STAGEB;
        uint32_t bb = ab + AHALFS * 2;
#pragma unroll
        for (int p = 0; p < 4; p++) {          // A: 128r x 64h = 1024 cp16
            int idx = tid + p * 256;
            int r = idx >> 3, seg = (idx & 7) << 3;
            cp16(ab + (uint32_t)(r * AP + seg) * 2, Ac + (size_t)r * D_ + seg);
        }
#pragma unroll
        for (int p = 0; p < 2; p++) {          // B: 64k x 64h = 512 cp16
            int idx = tid + p * 256;
            int kb = idx >> 3, seg = (idx & 7) << 3;
            cp16(bb + (uint32_t)(kb * BPn + seg) * 2, Bc + (size_t)kb * D_ + seg);
        }
        CP_COMMIT();
    };

    copy_chunk(0, 0);

    for (int c = 0; c < NC; c++) {
        const int buf = c & 1;
        if (c + 1 < NC) { copy_chunk(c + 1, buf ^ 1); CP_WAIT(1); }
        else            { CP_WAIT(0); }
        __syncthreads();

        uint32_t Asb = sbase + (uint32_t)buf * STAGEB;
        uint32_t Bsb = Asb + AHALFS * 2;

#pragma unroll
        for (int kt = 0; kt < 4; kt++) {
            uint32_t a[4][4];
#pragma unroll
            for (int i = 0; i < 4; i++) {
                int row  = m0w + 16 * i + (ml & 1) * 8 + rw;
                int colh = kt * 16 + ((ml >> 1) & 1) * 8;
                ldsm4(a[i], Asb + (uint32_t)(row * AP + colh) * 2);
            }
            uint32_t bf[4];
            int rowb = kt * 16 + (ml & 1) * 8 + rw;
            int colb = n0w + ((ml >> 1) & 1) * 8;
            ldsm4t(bf, Bsb + (uint32_t)(rowb * BPn + colb) * 2);
#pragma unroll
            for (int i = 0; i < 4; i++) {
                mma_f16(acc[i][0], a[i], bf[0], bf[1]);
                mma_f16(acc[i][1], a[i], bf[2], bf[3]);
            }
        }
        __syncthreads();   // all warps done with buf before it is re-filled
    }

#pragma unroll
    for (int i = 0; i < 4; i++) {
        int r0 = by * 128 + m0w + 16 * i + g;
        int r1 = r0 + 8;
#pragma unroll
        for (int j = 0; j < 2; j++) {
            int cc = bx * 64 + n0w + 8 * j + 2 * tig;
            if (MODE == 1) {
                __half2* C2 = (__half2*)C;
                C2[(size_t)r0 * (N / 2) + cc / 2] =
                    __floats2half2_rn(acc[i][j][0] * scale, acc[i][j][1] * scale);
                C2[(size_t)r1 * (N / 2) + cc / 2] =
                    __floats2half2_rn(acc[i][j][2] * scale, acc[i][j][3] * scale);
            } else {
                float* Cf = (float*)C;
                *(float2*)&Cf[(size_t)r0 * N + cc] =
                    make_float2(acc[i][j][0], acc[i][j][1]);
                *(float2*)&Cf[(size_t)r1 * N + cc] =
                    make_float2(acc[i][j][2], acc[i][j][3]);
            }
        }
    }
}

// Fused Q/K/V projection: grid (48, 32); bx/16 selects weight+destination.
__global__ __launch_bounds__(256, 4) void gemm_qkv(const __half* __restrict__ x,
                                                   const __half* __restrict__ Wr,
                                                   __half* __restrict__ Qo,
                                                   __half* __restrict__ Ko,
                                                   __half* __restrict__ Vo)
{
    extern __shared__ __half smh[];
    const int sel = blockIdx.x >> 4;
    const int bx  = blockIdx.x & 15;
    const __half* W = Wr + (size_t)sel * D_ * D_;
    __half* Cd = (sel == 0) ? Qo : (sel == 1) ? Ko : Vo;
    float scale = (sel == 0) ? 0.18033688f : 1.0f;   // log2(e)/8
    gemm_body<1>(x, W, Cd, bx, blockIdx.y, scale, smh);
}

__global__ __launch_bounds__(256, 4) void gemm_out(const __half* __restrict__ A,
                                                   const __half* __restrict__ W,
                                                   float* __restrict__ C)
{
    extern __shared__ __half smh[];
    gemm_body<0>(A, W, C, blockIdx.x, blockIdx.y, 1.0f, smh);
}

// ---------------------------------------------------------------------------
// fp16 causal flash attention (R15 winner, unchanged): exp2-f16x2 softmax,
// ldmatrix fragments, V transposed by .trans, fp16 P direct to smem.
// ---------------------------------------------------------------------------
#define QP_    72
#define QHALFS (128 * QP_)               // 9216
#define KVBUF  (64 * QP_)                // 4608
#define OFF_K  QHALFS
#define OFF_V  (OFF_K + 2 * KVBUF)
#define ASMEM  ((OFF_V + 2 * KVBUF) * 2) // 55296 B

__global__ __launch_bounds__(256, 2) void attn_tc(const __half* __restrict__ Q,
                                                  const __half* __restrict__ K,
                                                  const __half* __restrict__ V,
                                                  __half* __restrict__ O)
{
    extern __shared__ __half smh[];
    __half* QP = smh;                    // Q tile, later P tile

    const int tid  = threadIdx.x;
    const int wid  = tid >> 5;
    const int lane = tid & 31;
    const int g    = lane >> 2;
    const int tig  = lane & 3;
    const int ml   = lane >> 3;
    const int rw   = lane & 7;

    const int qt = (int)gridDim.x - 1 - (int)blockIdx.x;   // heavy-first
    const int bh = blockIdx.y;
    const int b  = bh >> 4;
    const int h  = bh & 15;

    const size_t base = (size_t)b * S_ * D_ + (size_t)h * DK_;
    const __half* Qb = Q + base;
    const __half* Kb = K + base;
    const __half* Vb = V + base;
    __half*       Ob = O + base;

    const int q0  = qt * 128;
    const int r0p = wid * 16 + g;
    const uint32_t sb = smem_u32(smh);

    // ---- load Q tile ----
#pragma unroll
    for (int p = 0; p < 4; p++) {
        int idx = tid + p * 256;
        int r = idx >> 3, seg = (idx & 7) << 3;
        cp16(sb + (uint32_t)(r * QP_ + seg) * 2,
             Qb + (size_t)(q0 + r) * D_ + seg);
    }
    CP_COMMIT();

    auto copy_kv = [&](int t, int buf) {
        const __half* Kc = Kb + (size_t)(t * 64) * D_;
        const __half* Vc = Vb + (size_t)(t * 64) * D_;
#pragma unroll
        for (int p = 0; p < 2; p++) {
            int idx = tid + p * 256;
            int r = idx >> 3, seg = (idx & 7) << 3;
            cp16(sb + (uint32_t)(OFF_K + buf * KVBUF + r * QP_ + seg) * 2,
                 Kc + (size_t)r * D_ + seg);
            cp16(sb + (uint32_t)(OFF_V + buf * KVBUF + r * QP_ + seg) * 2,
                 Vc + (size_t)r * D_ + seg);
        }
        CP_COMMIT();
    };

    copy_kv(0, 0);

    CP_WAIT(1);
    __syncthreads();

    // ---- preload Q A-fragments (Q pre-scaled by log2e/8) ----
    uint32_t qf[4][4];
#pragma unroll
    for (int kt = 0; kt < 4; kt++) {
        int row  = wid * 16 + (ml & 1) * 8 + rw;
        int colh = kt * 16 + ((ml >> 1) & 1) * 8;
        ldsm4(qf[kt], sb + (uint32_t)(row * QP_ + colh) * 2);
    }
    __syncthreads();    // all warps read Q before P overwrites region

    float m0 = -1e30f, m1 = -1e30f, l0 = 0.f, l1 = 0.f;
    float o[8][4];
#pragma unroll
    for (int nt = 0; nt < 8; nt++)
#pragma unroll
        for (int c = 0; c < 4; c++) o[nt][c] = 0.f;

    const int qrow0 = q0 + r0p;
    const int qrow1 = qrow0 + 8;
    const int ntiles = 2 * qt + 2;

    for (int t = 0; t < ntiles; t++) {
        const int buf = t & 1;
        CP_WAIT(0);
        __syncthreads();            // tile t ready; all warps done with t-1
        if (t + 1 < ntiles) copy_kv(t + 1, buf ^ 1);

        const int kofs = OFF_K + buf * KVBUF;
        const int vofs = OFF_V + buf * KVBUF;
        const int kv0  = t * 64;

        // ---- scores (log2 units) = (Q*log2e/8) @ K^T ----
        float sacc[8][4];
#pragma unroll
        for (int nt = 0; nt < 8; nt++)
#pragma unroll
            for (int c = 0; c < 4; c++) sacc[nt][c] = 0.f;

#pragma unroll
        for (int kt = 0; kt < 4; kt++) {
#pragma unroll
            for (int np = 0; np < 4; np++) {
                uint32_t bf[4];
                int rowb = np * 16 + ((ml >> 1) & 1) * 8 + rw;
                int colb = kt * 16 + (ml & 1) * 8;
                ldsm4(bf, sb + (uint32_t)(kofs + rowb * QP_ + colb) * 2);
                mma_f16(sacc[2 * np + 0], qf[kt], bf[0], bf[1]);
                mma_f16(sacc[2 * np + 1], qf[kt], bf[2], bf[3]);
            }
        }

        // ---- causal mask ----
        if (kv0 + 63 > q0) {
#pragma unroll
            for (int nt = 0; nt < 8; nt++) {
                int c0 = kv0 + nt * 8 + 2 * tig;
                if (c0     > qrow0) sacc[nt][0] = -1e30f;
                if (c0 + 1 > qrow0) sacc[nt][1] = -1e30f;
                if (c0     > qrow1) sacc[nt][2] = -1e30f;
                if (c0 + 1 > qrow1) sacc[nt][3] = -1e30f;
            }
        }

        // ---- online softmax, exp2 f16x2 ----
        float rmax0 = -1e30f, rmax1 = -1e30f;
#pragma unroll
        for (int nt = 0; nt < 8; nt++) {
            rmax0 = fmaxf(rmax0, fmaxf(sacc[nt][0], sacc[nt][1]));
            rmax1 = fmaxf(rmax1, fmaxf(sacc[nt][2], sacc[nt][3]));
        }
        rmax0 = fmaxf(rmax0, __shfl_xor_sync(0xffffffffu, rmax0, 1));
        rmax0 = fmaxf(rmax0, __shfl_xor_sync(0xffffffffu, rmax0, 2));
        rmax1 = fmaxf(rmax1, __shfl_xor_sync(0xffffffffu, rmax1, 1));
        rmax1 = fmaxf(rmax1, __shfl_xor_sync(0xffffffffu, rmax1, 2));

        float mn0 = fmaxf(m0, rmax0), mn1 = fmaxf(m1, rmax1);
        float corr0 = exp2f(m0 - mn0), corr1 = exp2f(m1 - mn1);
        m0 = mn0; m1 = mn1;

        float ps0 = 0.f, ps1 = 0.f;
#pragma unroll
        for (int nt = 0; nt < 8; nt++) {
            __half2 p01 = hexp2_(__floats2half2_rn(sacc[nt][0] - m0,
                                                   sacc[nt][1] - m0));
            __half2 p23 = hexp2_(__floats2half2_rn(sacc[nt][2] - m1,
                                                   sacc[nt][3] - m1));
            *(__half2*)&QP[r0p * QP_ + nt * 8 + 2 * tig] = p01;
            *(__half2*)&QP[(r0p + 8) * QP_ + nt * 8 + 2 * tig] = p23;
            float2 f01 = __half22float2(p01);
            float2 f23 = __half22float2(p23);
            ps0 += f01.x + f01.y;
            ps1 += f23.x + f23.y;
            o[nt][0] *= corr0; o[nt][1] *= corr0;
            o[nt][2] *= corr1; o[nt][3] *= corr1;
        }
        l0 = l0 * corr0 + ps0;
        l1 = l1 * corr1 + ps1;
        __syncwarp();

        // ---- O += P @ V (V transposed by ldmatrix.trans) ----
#pragma unroll
        for (int kt = 0; kt < 4; kt++) {
            uint32_t av[4];
            int rowp = wid * 16 + (ml & 1) * 8 + rw;
            int colp = kt * 16 + ((ml >> 1) & 1) * 8;
            ldsm4(av, sb + (uint32_t)(rowp * QP_ + colp) * 2);
#pragma unroll
            for (int np = 0; np < 4; np++) {
                uint32_t bf[4];
                int rowv = kt * 16 + (ml & 1) * 8 + rw;
                int colv = np * 16 + ((ml >> 1) & 1) * 8;
                ldsm4t(bf, sb + (uint32_t)(vofs + rowv * QP_ + colv) * 2);
                mma_f16(o[2 * np + 0], av, bf[0], bf[1]);
                mma_f16(o[2 * np + 1], av, bf[2], bf[3]);
            }
        }
    }

    // ---- normalize and write fp16 ----
    l0 += __shfl_xor_sync(0xffffffffu, l0, 1);
    l0 += __shfl_xor_sync(0xffffffffu, l0, 2);
    l1 += __shfl_xor_sync(0xffffffffu, l1, 1);
    l1 += __shfl_xor_sync(0xffffffffu, l1, 2);
    float inv0 = 1.0f / l0, inv1 = 1.0f / l1;

#pragma unroll
    for (int nt = 0; nt < 8; nt++) {
        int cc = nt * 8 + 2 * tig;
        *(__half2*)&Ob[(size_t)qrow0 * D_ + cc] =
            __floats2half2_rn(o[nt][0] * inv0, o[nt][1] * inv0);
        *(__half2*)&Ob[(size_t)qrow1 * D_ + cc] =
            __floats2half2_rn(o[nt][2] * inv1, o[nt][3] * inv1);
    }
}

// ---------------------------------------------------------------------------
extern "C" void kernel_launch(void* const* d_in, const int* in_sizes, int n_in,
                              void* d_out, int out_size)
{
    (void)in_sizes; (void)n_in; (void)out_size;
    const float* x  = (const float*)d_in[0];
    const float* Wq = (const float*)d_in[1];
    const float* Wk = (const float*)d_in[2];
    const float* Wv = (const float*)d_in[3];
    const float* Wo = (const float*)d_in[4];
    float* out = (float*)d_out;

    __half *qp, *kp, *vp, *ap, *xh, *wh;
    cudaGetSymbolAddress((void**)&qp, g_Q);
    cudaGetSymbolAddress((void**)&kp, g_K);
    cudaGetSymbolAddress((void**)&vp, g_V);
    cudaGetSymbolAddress((void**)&ap, g_att);
    cudaGetSymbolAddress((void**)&xh, g_x16);
    cudaGetSymbolAddress((void**)&wh, g_w16);

    cudaFuncSetAttribute(gemm_qkv, cudaFuncAttributeMaxDynamicSharedMemorySize, GSMEM);
    cudaFuncSetAttribute(gemm_out, cudaFuncAttributeMaxDynamicSharedMemorySize, GSMEM);
    cudaFuncSetAttribute(attn_tc,  cudaFuncAttributeMaxDynamicSharedMemorySize, ASMEM);

    cvt_all<<<8192, 256>>>(x, Wq, Wk, Wv, Wo, (__half2*)xh, (__half2*)wh);

    gemm_qkv<<<dim3(48, MTOT / 128), 256, GSMEM>>>(xh, wh, qp, kp, vp);

    attn_tc<<<dim3(S_ / 128, B_ * H_), 256, ASMEM>>>(qp, kp, vp, ap);

    gemm_out<<<dim3(16, MTOT / 128), 256, GSMEM>>>(ap, wh + 3 * (size_t)D_ * D_, out);
}